// round 5
// baseline (speedup 1.0000x reference)
#include <cuda_runtime.h>

#define N 96
#define NPAD 97
#define NUM_ITERS 12           // contraction <=0.1/iter -> residual <=1e-12, invisible at fp32
#define NMAT (N * N)           // 9216 matrices
#define MAT_ELEMS (N * N)      // 9216 elements per matrix
#define RESCALE 0.015625f      // 1/64: keeps |b| bounded; ratio b[k]/b[s] is scale-invariant
#define CHUNK 4                // matrices per CTA (software pipeline depth)
#define QSTEPS 24              // load steps per matrix per thread (2304 float4 / 96 thr)
#define QS_PER_IT (QSTEPS / NUM_ITERS)   // 2

// Per-matrix contributions, laid out [k][m] so the reduction kernel reads coalesced.
__device__ float g_scratch[N * NMAT];

__device__ __forceinline__ float4 sig4(float4 z, float4 c, float4 w) {
    float4 o;
    o.x = 1.f / (1.f + __expf(-fmaf(w.x, z.x, c.x)));
    o.y = 1.f / (1.f + __expf(-fmaf(w.y, z.y, c.y)));
    o.z = 1.f / (1.f + __expf(-fmaf(w.z, z.z, c.z)));
    o.w = 1.f / (1.f + __expf(-fmaf(w.w, z.w, c.w)));
    return o;
}

__global__ __launch_bounds__(N, 3)
void rbc_power_iter_kernel(const float* __restrict__ r_zeros,
                           const float* __restrict__ r_const,
                           const float* __restrict__ weights_r,
                           const float* __restrict__ weights_t) {
    extern __shared__ float smem[];
    float* sAbuf[2] = { smem, smem + N * NPAD };          // 2 x 37.2 KB A tiles
    float* sb       = smem + 2 * N * NPAD;                // 2 x 96 b vectors (ping-pong)

    const int tid = threadIdx.x;
    const int m0  = blockIdx.x * CHUNK;

    // Per-thread constant staging coords: q = tid + k*96 -> elem idx 4q
    // i = 4k + tid/24, j = 4*(tid%24)  (one row-quad per (thread,k))
    const int tdiv = tid / 24;
    const int tj   = 4 * (tid - tdiv * 24);

    // ---- Prologue: fully load matrix m0 into buffer 0 ----
    {
        const long long base = (long long)m0 * MAT_ELEMS;
        const float4* rz4 = (const float4*)(r_zeros   + base);
        const float4* rc4 = (const float4*)(r_const   + base);
        const float4* wr4 = (const float4*)(weights_r + base);
        #pragma unroll 4
        for (int k = 0; k < QSTEPS; ++k) {
            int q = tid + k * N;
            float4 o = sig4(rz4[q], rc4[q], wr4[q]);
            float* dst = &sAbuf[0][(4 * k + tdiv) * NPAD + tj];
            dst[0] = o.x; dst[1] = o.y; dst[2] = o.z; dst[3] = o.w;
        }
    }
    __syncthreads();

    #pragma unroll 1
    for (int c = 0; c < CHUNK; ++c) {
        const int cur = c & 1;
        const int m   = m0 + c;

        // ---- cache my row in registers from the current buffer ----
        float a[N];
        {
            const float* row = &sAbuf[cur][tid * NPAD];
            #pragma unroll
            for (int j = 0; j < N; ++j) a[j] = row[j];
        }
        sb[tid] = 1.0f;                                    // sb[0] bank = b0

        // prefetch pointers for matrix m+1 (not dereferenced when pf == false)
        const bool pf = (c + 1 < CHUNK);
        const long long nbase = (long long)(m + 1) * MAT_ELEMS;
        const float4* rz4 = (const float4*)(r_zeros   + nbase);
        const float4* rc4 = (const float4*)(r_const   + nbase);
        const float4* wr4 = (const float4*)(weights_r + nbase);
        float* nbuf = sAbuf[cur ^ 1];
        __syncthreads();

        // ---- 12 pipelined iterations: matvec on m, 2 load-steps of m+1 ----
        float bi = 1.0f;
        #pragma unroll 1
        for (int it = 0; it < NUM_ITERS; ++it) {
            // issue prefetch loads early (latency hides under the matvec)
            float4 z0, c0, w0, z1, c1, w1;
            const int q0 = tid + (QS_PER_IT * it) * N;
            const int q1 = q0 + N;
            if (pf) {
                z0 = rz4[q0]; c0 = rc4[q0]; w0 = wr4[q0];
                z1 = rz4[q1]; c1 = rc4[q1]; w1 = wr4[q1];
            }

            const float4* bv4 = (const float4*)&sb[(it & 1) * N];
            float acc0 = 0.f, acc1 = 0.f, acc2 = 0.f, acc3 = 0.f;
            #pragma unroll
            for (int j = 0; j < N; j += 4) {
                float4 bv = bv4[j >> 2];                   // broadcast LDS.128
                acc0 = fmaf(a[j    ], bv.x, acc0);
                acc1 = fmaf(a[j + 1], bv.y, acc1);
                acc2 = fmaf(a[j + 2], bv.z, acc2);
                acc3 = fmaf(a[j + 3], bv.w, acc3);
            }
            bi = ((acc0 + acc1) + (acc2 + acc3)) * RESCALE;

            if (pf) {                                      // sigmoid + stage into next buffer
                float4 o0 = sig4(z0, c0, w0);
                float4 o1 = sig4(z1, c1, w1);
                const int k0 = QS_PER_IT * it;
                float* d0 = &nbuf[(4 * k0 + tdiv) * NPAD + tj];
                d0[0] = o0.x; d0[1] = o0.y; d0[2] = o0.z; d0[3] = o0.w;
                float* d1 = &nbuf[(4 * (k0 + 1) + tdiv) * NPAD + tj];
                d1[0] = o1.x; d1[1] = o1.y; d1[2] = o1.z; d1[3] = o1.w;
            }

            sb[((it & 1) ^ 1) * N + tid] = bi;
            __syncthreads();
        }

        // ---- contribution[k] = wt[s,t] * b[k] / b[s] (scale cancels) ----
        const int s = m / N;
        const float b_s = sb[(NUM_ITERS & 1) * N + s];
        g_scratch[tid * NMAT + m] = (bi / b_s) * weights_t[m];
        __syncthreads();                                   // protect sb before next re-init
    }
}

// Deterministic reduction over m for each k (fixed accumulation order every run).
__global__ __launch_bounds__(256)
void rbc_reduce_kernel(float* __restrict__ out) {
    const int k   = blockIdx.x;
    const int tid = threadIdx.x;
    __shared__ float sp[8];

    const float* src = &g_scratch[k * NMAT];
    float s = 0.f;
    #pragma unroll 4
    for (int i = tid; i < NMAT; i += 256) s += src[i];

    #pragma unroll
    for (int o = 16; o > 0; o >>= 1) s += __shfl_xor_sync(0xffffffffu, s, o);
    if ((tid & 31) == 0) sp[tid >> 5] = s;
    __syncthreads();
    if (tid < 8) {
        float v = sp[tid];
        #pragma unroll
        for (int o = 4; o > 0; o >>= 1) v += __shfl_xor_sync(0xffu, v, o);
        if (tid == 0) out[k] = v;
    }
}

extern "C" void kernel_launch(void* const* d_in, const int* in_sizes, int n_in,
                              void* d_out, int out_size) {
    // metadata order: x, r_zeros, r_const, max_error, weights_t, weights_r
    const float* r_zeros   = (const float*)d_in[1];
    const float* r_const   = (const float*)d_in[2];
    const float* weights_t = (const float*)d_in[4];
    const float* weights_r = (const float*)d_in[5];
    float* out = (float*)d_out;

    const int smem_bytes = (2 * N * NPAD + 2 * N) * (int)sizeof(float);  // 75264 B
    cudaFuncSetAttribute(rbc_power_iter_kernel,
                         cudaFuncAttributeMaxDynamicSharedMemorySize, smem_bytes);

    rbc_power_iter_kernel<<<NMAT / CHUNK, N, smem_bytes>>>(r_zeros, r_const,
                                                           weights_r, weights_t);
    rbc_reduce_kernel<<<N, 256>>>(out);
}

// round 9
// speedup vs baseline: 1.7695x; 1.7695x over previous
#include <cuda_runtime.h>

#define N 96
#define NPAD 97
#define NUM_ITERS 8            // contraction ~0.04/iter; residual ~1e-9 << 1e-3 gate (12 iters measured identical to 50)
#define NMAT (N * N)           // 9216 matrices
#define MAT_ELEMS (N * N)      // 9216 elements per matrix
#define RESCALE 0.015625f      // 1/64: keeps |b| bounded; ratio b[k]/b[s] is scale-invariant
#define CHUNK 8                // matrices per CTA; prologue amortized to 1/8
#define QSG 3                  // load-steps per iteration group (24 steps / 8 iters)

// Per-matrix contributions, laid out [k][m] so the reduction kernel reads coalesced.
__device__ float g_scratch[N * NMAT];

__device__ __forceinline__ float4 sig4(float4 z, float4 c, float4 w) {
    float4 o;
    o.x = 1.f / (1.f + __expf(-fmaf(w.x, z.x, c.x)));
    o.y = 1.f / (1.f + __expf(-fmaf(w.y, z.y, c.y)));
    o.z = 1.f / (1.f + __expf(-fmaf(w.z, z.z, c.z)));
    o.w = 1.f / (1.f + __expf(-fmaf(w.w, z.w, c.w)));
    return o;
}

__global__ __launch_bounds__(N, 4)
void rbc_power_iter_kernel(const float* __restrict__ r_zeros,
                           const float* __restrict__ r_const,
                           const float* __restrict__ weights_r,
                           const float* __restrict__ weights_t) {
    // SINGLE A buffer: sA is fully consumed by the register row-cache at matrix
    // start, so next matrix stages into the SAME buffer during iterations.
    __shared__ float sA[N * NPAD];                 // 37.9KB -> occupancy 4 (static, <48KB)
    __shared__ __align__(16) float sb[2 * N];      // ping-pong b vector

    const int tid  = threadIdx.x;
    const int m0   = blockIdx.x * CHUNK;
    const int tdiv = tid / 24;                     // staging coords: step k -> row 4k+tdiv, col tj
    const int tj   = 4 * (tid - tdiv * 24);

    // ---- Prologue: fully load matrix m0 (high MLP burst) ----
    {
        const long long base = (long long)m0 * MAT_ELEMS;
        const float4* rz4 = (const float4*)(r_zeros   + base);
        const float4* rc4 = (const float4*)(r_const   + base);
        const float4* wr4 = (const float4*)(weights_r + base);
        #pragma unroll 4
        for (int k = 0; k < 24; ++k) {
            int q = tid + k * N;
            float4 o = sig4(rz4[q], rc4[q], wr4[q]);
            float* dst = &sA[(4 * k + tdiv) * NPAD + tj];
            dst[0] = o.x; dst[1] = o.y; dst[2] = o.z; dst[3] = o.w;
        }
    }
    __syncthreads();

    #pragma unroll 1
    for (int c = 0; c < CHUNK; ++c) {
        const int m = m0 + c;

        // ---- row-cache: after this sync, sA is dead and reusable ----
        float a[N];
        {
            const float* row = &sA[tid * NPAD];
            #pragma unroll
            for (int j = 0; j < N; ++j) a[j] = row[j];
        }
        sb[tid] = 1.0f;
        __syncthreads();

        const bool pf = (c + 1 < CHUNK);
        const long long nbase = (long long)(m + 1) * MAT_ELEMS;
        const float4* rz4 = (const float4*)(r_zeros   + nbase);
        const float4* rc4 = (const float4*)(r_const   + nbase);
        const float4* wr4 = (const float4*)(weights_r + nbase);

        float4 pz[QSG], pc[QSG], pw[QSG];          // one in-flight load group (36 regs)

        float bi = 1.0f;
        #pragma unroll 1
        for (int it = 0; it < NUM_ITERS; ++it) {
            // consume group issued at it-1 (one full iteration of latency elapsed)
            if (pf && it > 0) {
                const int k0 = QSG * (it - 1);
                #pragma unroll
                for (int u = 0; u < QSG; ++u) {
                    float4 o = sig4(pz[u], pc[u], pw[u]);
                    float* dst = &sA[(4 * (k0 + u) + tdiv) * NPAD + tj];
                    dst[0] = o.x; dst[1] = o.y; dst[2] = o.z; dst[3] = o.w;
                }
            }
            // issue this iteration's group: lands during matvec + next matvec
            if (pf) {
                #pragma unroll
                for (int u = 0; u < QSG; ++u) {
                    int q = tid + (QSG * it + u) * N;
                    pz[u] = rz4[q]; pc[u] = rc4[q]; pw[u] = wr4[q];
                }
            }
            // matvec: register row x broadcast b, 4-way ILP
            const float4* bv4 = (const float4*)&sb[(it & 1) * N];
            float acc0 = 0.f, acc1 = 0.f, acc2 = 0.f, acc3 = 0.f;
            #pragma unroll
            for (int j = 0; j < N; j += 4) {
                float4 bv = bv4[j >> 2];
                acc0 = fmaf(a[j    ], bv.x, acc0);
                acc1 = fmaf(a[j + 1], bv.y, acc1);
                acc2 = fmaf(a[j + 2], bv.z, acc2);
                acc3 = fmaf(a[j + 3], bv.w, acc3);
            }
            bi = ((acc0 + acc1) + (acc2 + acc3)) * RESCALE;
            sb[((it & 1) ^ 1) * N + tid] = bi;
            __syncthreads();
        }

        // tail: consume the last group (issued at it = NUM_ITERS-1)
        if (pf) {
            const int k0 = QSG * (NUM_ITERS - 1);
            #pragma unroll
            for (int u = 0; u < QSG; ++u) {
                float4 o = sig4(pz[u], pc[u], pw[u]);
                float* dst = &sA[(4 * (k0 + u) + tdiv) * NPAD + tj];
                dst[0] = o.x; dst[1] = o.y; dst[2] = o.z; dst[3] = o.w;
            }
        }

        // ---- contribution[k] = wt[s,t] * b[k] / b[s] (scale cancels) ----
        const int s = m / N;
        const float b_s = sb[s];                   // final b lives in sb[0..N)
        g_scratch[tid * NMAT + m] = (bi / b_s) * weights_t[m];
        __syncthreads();                           // sb + sA safe before next matrix
    }
}

// Deterministic reduction over m for each k (fixed accumulation order every run).
__global__ __launch_bounds__(256)
void rbc_reduce_kernel(float* __restrict__ out) {
    const int k   = blockIdx.x;
    const int tid = threadIdx.x;
    __shared__ float sp[8];

    const float4* src4 = (const float4*)&g_scratch[k * NMAT];
    float s = 0.f;
    #pragma unroll 3
    for (int i = tid; i < NMAT / 4; i += 256) {
        float4 v = src4[i];
        s += (v.x + v.y) + (v.z + v.w);
    }

    #pragma unroll
    for (int o = 16; o > 0; o >>= 1) s += __shfl_xor_sync(0xffffffffu, s, o);
    if ((tid & 31) == 0) sp[tid >> 5] = s;
    __syncthreads();
    if (tid < 8) {
        float v = sp[tid];
        #pragma unroll
        for (int o = 4; o > 0; o >>= 1) v += __shfl_xor_sync(0xffu, v, o);
        if (tid == 0) out[k] = v;
    }
}

extern "C" void kernel_launch(void* const* d_in, const int* in_sizes, int n_in,
                              void* d_out, int out_size) {
    // metadata order: x, r_zeros, r_const, max_error, weights_t, weights_r
    const float* r_zeros   = (const float*)d_in[1];
    const float* r_const   = (const float*)d_in[2];
    const float* weights_t = (const float*)d_in[4];
    const float* weights_r = (const float*)d_in[5];
    float* out = (float*)d_out;

    rbc_power_iter_kernel<<<NMAT / CHUNK, N>>>(r_zeros, r_const, weights_r, weights_t);
    rbc_reduce_kernel<<<N, 256>>>(out);
}

// round 12
// speedup vs baseline: 1.9310x; 1.0913x over previous
#include <cuda_runtime.h>

#define N 96
#define NPAD 97
#define NUM_ITERS 8            // contraction ~0.04/iter; residual ~1e-9 << 1e-3 gate
#define NMAT (N * N)           // 9216 matrices
#define MAT_ELEMS (N * N)      // 9216 elements per matrix
#define RESCALE 0.015625f      // 1/64: keeps |b| bounded; ratio b[k]/b[s] is scale-invariant
#define CHUNK 16               // matrices per CTA; grid 576 <= 592 resident -> SINGLE WAVE
#define NCTA (NMAT / CHUNK)    // 576
#define QSG 3                  // load-steps per iteration group (24 steps / 8 iters)

// Per-CTA partial sums, laid out [k][cta] so the reduction kernel reads coalesced.
__device__ float g_scratch[N * NCTA];

__device__ __forceinline__ float4 sig4(float4 z, float4 c, float4 w) {
    float4 o;
    o.x = 1.f / (1.f + __expf(-fmaf(w.x, z.x, c.x)));
    o.y = 1.f / (1.f + __expf(-fmaf(w.y, z.y, c.y)));
    o.z = 1.f / (1.f + __expf(-fmaf(w.z, z.z, c.z)));
    o.w = 1.f / (1.f + __expf(-fmaf(w.w, z.w, c.w)));
    return o;
}

__global__ __launch_bounds__(N, 4)
void rbc_power_iter_kernel(const float* __restrict__ r_zeros,
                           const float* __restrict__ r_const,
                           const float* __restrict__ weights_r,
                           const float* __restrict__ weights_t) {
    // SINGLE A buffer: sA is fully consumed by the register row-cache at matrix
    // start, so next matrix stages into the SAME buffer during iterations.
    __shared__ float sA[N * NPAD];                 // 37.9KB -> occupancy 4
    __shared__ __align__(16) float sb[2 * N];      // ping-pong b vector

    const int tid  = threadIdx.x;
    const int m0   = blockIdx.x * CHUNK;
    const int tdiv = tid / 24;                     // staging coords: step k -> row 4k+tdiv, col tj
    const int tj   = 4 * (tid - tdiv * 24);

    // ---- Prologue: fully load matrix m0 (high MLP burst; once per CTA, single wave) ----
    {
        const long long base = (long long)m0 * MAT_ELEMS;
        const float4* rz4 = (const float4*)(r_zeros   + base);
        const float4* rc4 = (const float4*)(r_const   + base);
        const float4* wr4 = (const float4*)(weights_r + base);
        #pragma unroll 4
        for (int k = 0; k < 24; ++k) {
            int q = tid + k * N;
            float4 o = sig4(rz4[q], rc4[q], wr4[q]);
            float* dst = &sA[(4 * k + tdiv) * NPAD + tj];
            dst[0] = o.x; dst[1] = o.y; dst[2] = o.z; dst[3] = o.w;
        }
    }
    __syncthreads();

    float ctasum = 0.f;                            // thread tid owns output index k=tid

    #pragma unroll 1
    for (int c = 0; c < CHUNK; ++c) {
        const int m = m0 + c;

        // ---- row-cache: after this sync, sA is dead and reusable ----
        float a[N];
        {
            const float* row = &sA[tid * NPAD];
            #pragma unroll
            for (int j = 0; j < N; ++j) a[j] = row[j];
        }
        sb[tid] = 1.0f;
        __syncthreads();

        const bool pf = (c + 1 < CHUNK);
        const long long nbase = (long long)(m + 1) * MAT_ELEMS;
        const float4* rz4 = (const float4*)(r_zeros   + nbase);
        const float4* rc4 = (const float4*)(r_const   + nbase);
        const float4* wr4 = (const float4*)(weights_r + nbase);

        float4 pz[QSG], pc[QSG], pw[QSG];          // one in-flight load group (36 regs)

        float bi = 1.0f;
        #pragma unroll 1
        for (int it = 0; it < NUM_ITERS; ++it) {
            // consume group issued at it-1 (one full iteration of latency elapsed)
            if (pf && it > 0) {
                const int k0 = QSG * (it - 1);
                #pragma unroll
                for (int u = 0; u < QSG; ++u) {
                    float4 o = sig4(pz[u], pc[u], pw[u]);
                    float* dst = &sA[(4 * (k0 + u) + tdiv) * NPAD + tj];
                    dst[0] = o.x; dst[1] = o.y; dst[2] = o.z; dst[3] = o.w;
                }
            }
            // issue this iteration's group: lands during matvec + next matvec
            if (pf) {
                #pragma unroll
                for (int u = 0; u < QSG; ++u) {
                    int q = tid + (QSG * it + u) * N;
                    pz[u] = rz4[q]; pc[u] = rc4[q]; pw[u] = wr4[q];
                }
            }
            // matvec: register row x broadcast b, 4-way ILP
            const float4* bv4 = (const float4*)&sb[(it & 1) * N];
            float acc0 = 0.f, acc1 = 0.f, acc2 = 0.f, acc3 = 0.f;
            #pragma unroll
            for (int j = 0; j < N; j += 4) {
                float4 bv = bv4[j >> 2];
                acc0 = fmaf(a[j    ], bv.x, acc0);
                acc1 = fmaf(a[j + 1], bv.y, acc1);
                acc2 = fmaf(a[j + 2], bv.z, acc2);
                acc3 = fmaf(a[j + 3], bv.w, acc3);
            }
            bi = ((acc0 + acc1) + (acc2 + acc3)) * RESCALE;
            sb[((it & 1) ^ 1) * N + tid] = bi;
            __syncthreads();
        }

        // tail: consume the last group (issued at it = NUM_ITERS-1)
        if (pf) {
            const int k0 = QSG * (NUM_ITERS - 1);
            #pragma unroll
            for (int u = 0; u < QSG; ++u) {
                float4 o = sig4(pz[u], pc[u], pw[u]);
                float* dst = &sA[(4 * (k0 + u) + tdiv) * NPAD + tj];
                dst[0] = o.x; dst[1] = o.y; dst[2] = o.z; dst[3] = o.w;
            }
        }

        // ---- accumulate contribution[k=tid] = wt[s,t] * b[k] / b[s] (scale cancels) ----
        const int s = m / N;
        const float b_s = sb[s];                   // final b lives in sb[0..N)
        ctasum = fmaf(bi / b_s, weights_t[m], ctasum);
        __syncthreads();                           // sb + sA safe before next matrix
    }

    g_scratch[tid * NCTA + blockIdx.x] = ctasum;   // one coalesced write per CTA
}

// Deterministic reduction over 576 CTA partials for each k.
__global__ __launch_bounds__(256)
void rbc_reduce_kernel(float* __restrict__ out) {
    const int k   = blockIdx.x;
    const int tid = threadIdx.x;
    __shared__ float sp[8];

    const float4* src4 = (const float4*)&g_scratch[k * NCTA];
    float s = 0.f;
    if (tid < NCTA / 4) {                          // 144 float4s
        float4 v = src4[tid];
        s = (v.x + v.y) + (v.z + v.w);
    }

    #pragma unroll
    for (int o = 16; o > 0; o >>= 1) s += __shfl_xor_sync(0xffffffffu, s, o);
    if ((tid & 31) == 0) sp[tid >> 5] = s;
    __syncthreads();
    if (tid < 8) {
        float v = sp[tid];
        #pragma unroll
        for (int o = 4; o > 0; o >>= 1) v += __shfl_xor_sync(0xffu, v, o);
        if (tid == 0) out[k] = v;
    }
}

extern "C" void kernel_launch(void* const* d_in, const int* in_sizes, int n_in,
                              void* d_out, int out_size) {
    // metadata order: x, r_zeros, r_const, max_error, weights_t, weights_r
    const float* r_zeros   = (const float*)d_in[1];
    const float* r_const   = (const float*)d_in[2];
    const float* weights_t = (const float*)d_in[4];
    const float* weights_r = (const float*)d_in[5];
    float* out = (float*)d_out;

    rbc_power_iter_kernel<<<NCTA, N>>>(r_zeros, r_const, weights_r, weights_t);
    rbc_reduce_kernel<<<N, 256>>>(out);
}